// round 5
// baseline (speedup 1.0000x reference)
#include <cuda_runtime.h>
#include <math.h>

// Problem constants (fixed by setup_inputs)
#define Bc 128          // batch
#define Nc 96           // num deltas
#define Dc 3072         // C*H*W
#define Kc 10           // classes
#define RPW 4           // rows (n-values) per warp, same b
#define WARPS 8
#define THREADS (WARPS*32)               // 256
#define NGROUPS (Bc * (Nc / RPW))        // 3072 warp-groups
#define BLOCKS1 (NGROUPS / WARPS)        // 384

__device__ float g_Wt[Kc * Dc];          // transposed W: [K][D]
__device__ float g_l1[Bc * Nc];
__device__ float g_l2[Bc * Nc];
__device__ float g_part[Bc];

// ---- packed f32x2 helpers (Blackwell FFMA2 only reachable via PTX) ----
__device__ __forceinline__ unsigned long long pack2(float lo, float hi) {
    unsigned long long r;
    asm("mov.b64 %0, {%1, %2};" : "=l"(r) : "f"(lo), "f"(hi));
    return r;
}
__device__ __forceinline__ void unpack2(float& lo, float& hi, unsigned long long v) {
    asm("mov.b64 {%0, %1}, %2;" : "=f"(lo), "=f"(hi) : "l"(v));
}
#define FMA2(d, a, b, c) \
    asm("fma.rn.f32x2 %0, %1, %2, %3;" : "=l"(d) : "l"(a), "l"(b), "l"(c))

__device__ __forceinline__ float clip01(float v) {
    return fminf(fmaxf(v, 0.0f), 1.0f);
}

// One-shot W transpose: W[d][k] -> g_Wt[k][d] (coalesced read, tiny)
__global__ void transpose_W_kernel(const float* __restrict__ Wm)
{
    int idx = blockIdx.x * blockDim.x + threadIdx.x;
    if (idx < Dc * Kc) {
        int d = idx / Kc, k = idx % Kc;
        g_Wt[k * Dc + d] = Wm[idx];
    }
}

__global__ __launch_bounds__(THREADS, 2)
void logits_kernel(const float* __restrict__ imgs,
                   const float* __restrict__ deltas,
                   const float* __restrict__ bias,
                   const int*   __restrict__ labels)
{
    const int warp = threadIdx.x >> 5;
    const int lane = threadIdx.x & 31;
    const int g    = blockIdx.x * WARPS + warp;   // 0..3071
    const int b    = g % Bc;
    const int n0   = (g / Bc) * RPW;

    const float4* img4 = (const float4*)(imgs + (size_t)b * Dc);
    const float4* dp0 = (const float4*)(deltas + ((size_t)(n0 + 0) * Bc + b) * Dc);
    const float4* dp1 = (const float4*)(deltas + ((size_t)(n0 + 1) * Bc + b) * Dc);
    const float4* dp2 = (const float4*)(deltas + ((size_t)(n0 + 2) * Bc + b) * Dc);
    const float4* dp3 = (const float4*)(deltas + ((size_t)(n0 + 3) * Bc + b) * Dc);

    // packed accumulators: acc[r][k] holds (partial_even, partial_odd)
    unsigned long long acc[RPW][Kc];
#pragma unroll
    for (int r = 0; r < RPW; r++)
#pragma unroll
        for (int k = 0; k < Kc; k++) acc[r][k] = 0ULL;

    for (int i = 0; i < Dc / 128; i++) {
        const int e = i * 32 + lane;            // float4 index within row
        float4 xi = __ldg(img4 + e);
        float4 d0 = __ldcs(dp0 + e);
        float4 d1 = __ldcs(dp1 + e);
        float4 d2 = __ldcs(dp2 + e);
        float4 d3 = __ldcs(dp3 + e);

        unsigned long long xp[RPW][2];
        {
            float a0 = clip01(xi.x + d0.x), a1 = clip01(xi.y + d0.y);
            float a2 = clip01(xi.z + d0.z), a3 = clip01(xi.w + d0.w);
            xp[0][0] = pack2(a0, a1); xp[0][1] = pack2(a2, a3);
        }
        {
            float a0 = clip01(xi.x + d1.x), a1 = clip01(xi.y + d1.y);
            float a2 = clip01(xi.z + d1.z), a3 = clip01(xi.w + d1.w);
            xp[1][0] = pack2(a0, a1); xp[1][1] = pack2(a2, a3);
        }
        {
            float a0 = clip01(xi.x + d2.x), a1 = clip01(xi.y + d2.y);
            float a2 = clip01(xi.z + d2.z), a3 = clip01(xi.w + d2.w);
            xp[2][0] = pack2(a0, a1); xp[2][1] = pack2(a2, a3);
        }
        {
            float a0 = clip01(xi.x + d3.x), a1 = clip01(xi.y + d3.y);
            float a2 = clip01(xi.z + d3.z), a3 = clip01(xi.w + d3.w);
            xp[3][0] = pack2(a0, a1); xp[3][1] = pack2(a2, a3);
        }

#pragma unroll
        for (int k = 0; k < Kc; k++) {
            ulonglong2 w2 = __ldg((const ulonglong2*)(g_Wt + (size_t)k * Dc) + e);
#pragma unroll
            for (int r = 0; r < RPW; r++) {
                FMA2(acc[r][k], xp[r][0], w2.x, acc[r][k]);
                FMA2(acc[r][k], xp[r][1], w2.y, acc[r][k]);
            }
        }
    }

    // Per-row epilogue: warp reduce 10 logits, compute loss1/loss2
#pragma unroll
    for (int r = 0; r < RPW; r++) {
        float lg[Kc];
#pragma unroll
        for (int k = 0; k < Kc; k++) {
            float lo, hi;
            unpack2(lo, hi, acc[r][k]);
            float v = lo + hi;
            v += __shfl_xor_sync(0xFFFFFFFFu, v, 16);
            v += __shfl_xor_sync(0xFFFFFFFFu, v, 8);
            v += __shfl_xor_sync(0xFFFFFFFFu, v, 4);
            v += __shfl_xor_sync(0xFFFFFFFFu, v, 2);
            v += __shfl_xor_sync(0xFFFFFFFFu, v, 1);
            lg[k] = v;
        }
        if (lane == 0) {
#pragma unroll
            for (int k = 0; k < Kc; k++) lg[k] += __ldg(bias + k);

            // argmax (first occurrence, matches top_k tie rule)
            float m = lg[0]; int t1 = 0;
#pragma unroll
            for (int k = 1; k < Kc; k++)
                if (lg[k] > m) { m = lg[k]; t1 = k; }

            float s = 0.0f;
#pragma unroll
            for (int k = 0; k < Kc; k++) s += expf(lg[k] - m);
            float lse = m + logf(s);

            int lab = __ldg(labels + b);
            float logit_lab = lg[0];
#pragma unroll
            for (int k = 1; k < Kc; k++)
                if (k == lab) logit_lab = lg[k];
            float loss1 = lse - logit_lab;

            // second-best (first occurrence among k != t1)
            float m2 = -INFINITY; int t2 = 0;
#pragma unroll
            for (int k = 0; k < Kc; k++)
                if (k != t1 && lg[k] > m2) { m2 = lg[k]; t2 = k; }
            float logit_t2 = lg[0];
#pragma unroll
            for (int k = 1; k < Kc; k++)
                if (k == t2) logit_t2 = lg[k];

            float loss2 = (t1 == lab) ? (lse - logit_t2) : -10000.0f;

            g_l1[b * Nc + (n0 + r)] = loss1;
            g_l2[b * Nc + (n0 + r)] = loss2;
        }
    }
}

// Per-batch-row stable rank-select (replicates stable argsort exactly)
__global__ void select_kernel(const int* __restrict__ indp)
{
    __shared__ float sd[Nc];
    __shared__ float sl1[Nc];
    __shared__ float sSel;

    const int b = blockIdx.x;
    const int j = threadIdx.x;   // 0..95

    float l1v = 0.0f, l2v = 0.0f, dv = 0.0f;
    if (j < Nc) {
        l1v = g_l1[b * Nc + j];
        l2v = g_l2[b * Nc + j];
        dv  = l1v - l2v;
        sd[j]  = dv;
        sl1[j] = l1v;
    }
    __syncthreads();

    const int ind = __ldg(indp);
    if (j < Nc) {
        int cnt = 0;
        for (int i = 0; i < Nc; i++) {
            float di = sd[i];
            cnt += (di < dv) || (di == dv && i < j);
        }
        if (cnt == ind) sSel = l2v;   // exactly one j satisfies this
    }
    __syncthreads();

    if (j == 0) {
        float s = 0.0f;
        for (int i = 0; i < Nc; i++) s += sl1[i];
        g_part[b] = s / (float)Nc - sSel;
    }
}

__global__ void reduce_kernel(float* __restrict__ out)
{
    if (threadIdx.x == 0) {
        float a = 0.0f;
#pragma unroll
        for (int i = 0; i < Bc; i++) a += g_part[i];
        out[0] = a / (float)Bc;
    }
}

extern "C" void kernel_launch(void* const* d_in, const int* in_sizes, int n_in,
                              void* d_out, int out_size)
{
    const float* imgs   = (const float*)d_in[0];
    const float* deltas = (const float*)d_in[1];
    const float* Wm     = (const float*)d_in[2];
    const float* bias   = (const float*)d_in[3];
    const int*   labels = (const int*)d_in[4];
    const int*   indp   = (const int*)d_in[5];
    float* out = (float*)d_out;

    transpose_W_kernel<<<(Dc * Kc + 255) / 256, 256>>>(Wm);
    logits_kernel<<<BLOCKS1, THREADS>>>(imgs, deltas, bias, labels);
    select_kernel<<<Bc, Nc>>>(indp);
    reduce_kernel<<<1, 32>>>(out);
}

// round 6
// speedup vs baseline: 1.2851x; 1.2851x over previous
#include <cuda_runtime.h>
#include <math.h>

// Problem constants (fixed by setup_inputs)
#define Bc 128          // batch
#define Nc 96           // num deltas
#define Dc 3072         // C*H*W
#define Kc 10           // classes
#define RPW 4           // rows (n-values) per warp-unit, same b
#define WARPS 16
#define THREADS (WARPS*32)               // 512
#define NUNITS (Bc * (Nc / RPW))         // 3072 units
#define GRID1 96                         // 96 CTAs * 16 warps = 1536 warps, 2 units each
#define WSLOTS (GRID1 * WARPS)           // 1536
#define SMEM_BYTES (Kc * Dc * 4)         // 122880 B

__device__ float g_l1[Bc * Nc];
__device__ float g_l2[Bc * Nc];
__device__ float g_part[Bc];

// ---- packed f32x2 helpers (Blackwell FFMA2 only reachable via PTX) ----
__device__ __forceinline__ unsigned long long pack2(float lo, float hi) {
    unsigned long long r;
    asm("mov.b64 %0, {%1, %2};" : "=l"(r) : "f"(lo), "f"(hi));
    return r;
}
__device__ __forceinline__ void unpack2(float& lo, float& hi, unsigned long long v) {
    asm("mov.b64 {%0, %1}, %2;" : "=f"(lo), "=f"(hi) : "l"(v));
}
#define FMA2(d, a, b, c) \
    asm("fma.rn.f32x2 %0, %1, %2, %3;" : "=l"(d) : "l"(a), "l"(b), "l"(c))

__device__ __forceinline__ float clip01(float v) {
    return fminf(fmaxf(v, 0.0f), 1.0f);
}

__global__ __launch_bounds__(THREADS, 1)
void logits_kernel(const float* __restrict__ imgs,
                   const float* __restrict__ deltas,
                   const float* __restrict__ Wm,
                   const float* __restrict__ bias,
                   const int*   __restrict__ labels)
{
    extern __shared__ float sW[];   // [Kc][Dc], transposed from W[d][k]

    // Cooperative load+transpose of W (coalesced global reads), once per CTA
    for (int idx = threadIdx.x; idx < Dc * Kc; idx += THREADS) {
        int d = idx / Kc, k = idx % Kc;
        sW[k * Dc + d] = Wm[idx];
    }
    __syncthreads();

    const int warp  = threadIdx.x >> 5;
    const int lane  = threadIdx.x & 31;
    const int wslot = blockIdx.x * WARPS + warp;   // 0..1535

    // exactly 2 units per warp: u and u+1536 (same b, so img row is L1-warm)
    for (int u = wslot; u < NUNITS; u += WSLOTS) {
        const int b  = u & (Bc - 1);
        const int n0 = (u >> 7) * RPW;

        const float4* img4 = (const float4*)(imgs + (size_t)b * Dc);
        const float4* dp0 = (const float4*)(deltas + ((size_t)(n0 + 0) * Bc + b) * Dc);
        const float4* dp1 = (const float4*)(deltas + ((size_t)(n0 + 1) * Bc + b) * Dc);
        const float4* dp2 = (const float4*)(deltas + ((size_t)(n0 + 2) * Bc + b) * Dc);
        const float4* dp3 = (const float4*)(deltas + ((size_t)(n0 + 3) * Bc + b) * Dc);

        unsigned long long acc[RPW][Kc];
#pragma unroll
        for (int r = 0; r < RPW; r++)
#pragma unroll
            for (int k = 0; k < Kc; k++) acc[r][k] = 0ULL;

        // prefetch iteration 0
        float4 xi = __ldg(img4 + lane);
        float4 d0 = __ldcs(dp0 + lane);
        float4 d1 = __ldcs(dp1 + lane);
        float4 d2 = __ldcs(dp2 + lane);
        float4 d3 = __ldcs(dp3 + lane);

#pragma unroll 2
        for (int i = 0; i < Dc / 128; i++) {
            // issue next iteration's loads before consuming current
            float4 nxi, nd0, nd1, nd2, nd3;
            if (i + 1 < Dc / 128) {
                const int e = (i + 1) * 32 + lane;
                nxi = __ldg(img4 + e);
                nd0 = __ldcs(dp0 + e);
                nd1 = __ldcs(dp1 + e);
                nd2 = __ldcs(dp2 + e);
                nd3 = __ldcs(dp3 + e);
            }

            unsigned long long xp[RPW][2];
            xp[0][0] = pack2(clip01(xi.x + d0.x), clip01(xi.y + d0.y));
            xp[0][1] = pack2(clip01(xi.z + d0.z), clip01(xi.w + d0.w));
            xp[1][0] = pack2(clip01(xi.x + d1.x), clip01(xi.y + d1.y));
            xp[1][1] = pack2(clip01(xi.z + d1.z), clip01(xi.w + d1.w));
            xp[2][0] = pack2(clip01(xi.x + d2.x), clip01(xi.y + d2.y));
            xp[2][1] = pack2(clip01(xi.z + d2.z), clip01(xi.w + d2.w));
            xp[3][0] = pack2(clip01(xi.x + d3.x), clip01(xi.y + d3.y));
            xp[3][1] = pack2(clip01(xi.z + d3.z), clip01(xi.w + d3.w));

            const int e4 = i * 32 + lane;   // ulonglong2 index (16B granules)
#pragma unroll
            for (int k = 0; k < Kc; k++) {
                ulonglong2 w2 = *((const ulonglong2*)(sW + (size_t)k * Dc) + e4);
#pragma unroll
                for (int r = 0; r < RPW; r++) {
                    FMA2(acc[r][k], xp[r][0], w2.x, acc[r][k]);
                    FMA2(acc[r][k], xp[r][1], w2.y, acc[r][k]);
                }
            }

            xi = nxi; d0 = nd0; d1 = nd1; d2 = nd2; d3 = nd3;
        }

        // Per-row epilogue: warp reduce 10 logits, compute loss1/loss2
#pragma unroll
        for (int r = 0; r < RPW; r++) {
            float lg[Kc];
#pragma unroll
            for (int k = 0; k < Kc; k++) {
                float lo, hi;
                unpack2(lo, hi, acc[r][k]);
                float v = lo + hi;
                v += __shfl_xor_sync(0xFFFFFFFFu, v, 16);
                v += __shfl_xor_sync(0xFFFFFFFFu, v, 8);
                v += __shfl_xor_sync(0xFFFFFFFFu, v, 4);
                v += __shfl_xor_sync(0xFFFFFFFFu, v, 2);
                v += __shfl_xor_sync(0xFFFFFFFFu, v, 1);
                lg[k] = v;
            }
            if (lane == 0) {
#pragma unroll
                for (int k = 0; k < Kc; k++) lg[k] += __ldg(bias + k);

                // argmax (first occurrence, matches top_k tie rule)
                float m = lg[0]; int t1 = 0;
#pragma unroll
                for (int k = 1; k < Kc; k++)
                    if (lg[k] > m) { m = lg[k]; t1 = k; }

                float s = 0.0f;
#pragma unroll
                for (int k = 0; k < Kc; k++) s += expf(lg[k] - m);
                float lse = m + logf(s);

                int lab = __ldg(labels + b);
                float logit_lab = lg[0];
#pragma unroll
                for (int k = 1; k < Kc; k++)
                    if (k == lab) logit_lab = lg[k];
                float loss1 = lse - logit_lab;

                // second-best (first occurrence among k != t1)
                float m2 = -INFINITY; int t2 = 0;
#pragma unroll
                for (int k = 0; k < Kc; k++)
                    if (k != t1 && lg[k] > m2) { m2 = lg[k]; t2 = k; }
                float logit_t2 = lg[0];
#pragma unroll
                for (int k = 1; k < Kc; k++)
                    if (k == t2) logit_t2 = lg[k];

                float loss2 = (t1 == lab) ? (lse - logit_t2) : -10000.0f;

                g_l1[b * Nc + (n0 + r)] = loss1;
                g_l2[b * Nc + (n0 + r)] = loss2;
            }
        }
    }
}

// Per-batch-row stable rank-select (replicates stable argsort exactly)
__global__ void select_kernel(const int* __restrict__ indp)
{
    __shared__ float sd[Nc];
    __shared__ float sl1[Nc];
    __shared__ float sSel;

    const int b = blockIdx.x;
    const int j = threadIdx.x;   // 0..95

    float l1v = 0.0f, l2v = 0.0f, dv = 0.0f;
    if (j < Nc) {
        l1v = g_l1[b * Nc + j];
        l2v = g_l2[b * Nc + j];
        dv  = l1v - l2v;
        sd[j]  = dv;
        sl1[j] = l1v;
    }
    __syncthreads();

    const int ind = __ldg(indp);
    if (j < Nc) {
        int cnt = 0;
        for (int i = 0; i < Nc; i++) {
            float di = sd[i];
            cnt += (di < dv) || (di == dv && i < j);
        }
        if (cnt == ind) sSel = l2v;   // exactly one j satisfies this
    }
    __syncthreads();

    if (j == 0) {
        float s = 0.0f;
        for (int i = 0; i < Nc; i++) s += sl1[i];
        g_part[b] = s / (float)Nc - sSel;
    }
}

__global__ void reduce_kernel(float* __restrict__ out)
{
    if (threadIdx.x == 0) {
        float a = 0.0f;
#pragma unroll
        for (int i = 0; i < Bc; i++) a += g_part[i];
        out[0] = a / (float)Bc;
    }
}

extern "C" void kernel_launch(void* const* d_in, const int* in_sizes, int n_in,
                              void* d_out, int out_size)
{
    const float* imgs   = (const float*)d_in[0];
    const float* deltas = (const float*)d_in[1];
    const float* Wm     = (const float*)d_in[2];
    const float* bias   = (const float*)d_in[3];
    const int*   labels = (const int*)d_in[4];
    const int*   indp   = (const int*)d_in[5];
    float* out = (float*)d_out;

    cudaFuncSetAttribute(logits_kernel,
                         cudaFuncAttributeMaxDynamicSharedMemorySize, SMEM_BYTES);

    logits_kernel<<<GRID1, THREADS, SMEM_BYTES>>>(imgs, deltas, Wm, bias, labels);
    select_kernel<<<Bc, Nc>>>(indp);
    reduce_kernel<<<1, 32>>>(out);
}